// round 15
// baseline (speedup 1.0000x reference)
#include <cuda_runtime.h>
#include <cuda_bf16.h>
#include <cstdint>
#include <cmath>

typedef unsigned long long ull;
typedef __nv_bfloat16 bf16;
#define DM 768
#define NQ 256
#define NM 512

#define FMA2(acc, a, b) asm("fma.rn.f32x2 %0, %1, %2, %0;" : "+l"(acc) : "l"(a), "l"(b))
#define DUP2(d, s)      asm("mov.b64 %0, {%1, %1};" : "=l"(d) : "f"(s))
#define UNPK2(lo, hi, s) asm("mov.b64 {%0, %1}, %2;" : "=f"(lo), "=f"(hi) : "l"(s))

__device__ __forceinline__ uint32_t smem_u32(const void* p) {
    uint32_t a;
    asm("{ .reg .u64 t; cvta.to.shared.u64 t, %1; cvt.u32.u64 %0, t; }" : "=r"(a) : "l"(p));
    return a;
}
__device__ __forceinline__ void ldm4(uint32_t* r, uint32_t addr) {
    asm volatile("ldmatrix.sync.aligned.m8n8.x4.shared.b16 {%0,%1,%2,%3}, [%4];"
        : "=r"(r[0]), "=r"(r[1]), "=r"(r[2]), "=r"(r[3]) : "r"(addr));
}
__device__ __forceinline__ void mma16816(float* c, const uint32_t* a, const uint32_t* b) {
    asm volatile("mma.sync.aligned.m16n8k16.row.col.f32.bf16.bf16.f32 "
        "{%0,%1,%2,%3}, {%4,%5,%6,%7}, {%8,%9}, {%0,%1,%2,%3};"
        : "+f"(c[0]), "+f"(c[1]), "+f"(c[2]), "+f"(c[3])
        : "r"(a[0]), "r"(a[1]), "r"(a[2]), "r"(a[3]), "r"(b[0]), "r"(b[1]));
}

// ---------------- scratch ---------------------------------------------------
constexpr size_t F_ip   = 0;
constexpr size_t F_tp   = F_ip   + 512*768;
constexpr size_t F_W01  = F_tp   + 512*768;
constexpr size_t F_part = F_W01  + 768*256;
constexpr size_t F_Ah   = F_part + 48*256;
constexpr size_t F_At   = F_Ah   + 512*2048;
constexpr size_t F_w    = F_At   + 512*2048;
constexpr size_t F_END  = F_w    + 256*512*8;
__device__ __align__(16) float g_f[F_END];

constexpr size_t B_Qs   = 0;
constexpr size_t B_IMGs = B_Qs   + 2*256*768;
constexpr size_t B_TGTs = B_IMGs + 2*512*768;
constexpr size_t B_Wos  = B_TGTs + 2*512*768;
constexpr size_t B_WqT  = B_Wos  + 2*768*768;
constexpr size_t B_WiT  = B_WqT  + 2*768*768;
constexpr size_t B_WtT  = B_WiT  + 2*768*768;
constexpr size_t B_WiqT = B_WtT  + 2*768*768;
constexpr size_t B_WikT = B_WiqT + 2*768*768;
constexpr size_t B_WivT = B_WikT + 2*768*768;
constexpr size_t B_W1T  = B_WivT + 2*768*768;
constexpr size_t B_W2T  = B_W1T  + 2*256*768;
constexpr size_t B_qs   = B_W2T  + 2*64*256;
constexpr size_t B_dps  = B_qs   + 2*256*768;
constexpr size_t B_tps  = B_dps  + 2*512*768;
constexpr size_t B_qhs  = B_tps  + 2*512*768;
constexpr size_t B_kds  = B_qhs  + 2*256*768;
constexpr size_t B_vds  = B_kds  + 2*512*768;
constexpr size_t B_vts  = B_vds  + 2*512*768;
constexpr size_t B_W01T = B_vts  + 2*512*768;
constexpr size_t B_END  = B_W01T + 2*256*768;
__device__ __align__(16) bf16 g_b[B_END];

// ---------------- bf16-split MMA GEMM: 64x64 tiles, 2-stage pipelined -------
// Stage (bf16 elems): Ah@0 [64][40], Al@2560, Bh@5120 [64][40], Bl@7680.
// ldmatrix byte offsets: Al 5120B, Bh 10240B, Bl 15360B.
struct TCDesc {
    const bf16 *Ah, *Al, *Bh, *Bl;
    const float* bias;
    float* C;
    bf16 *Chi, *Clo;
    int lda, ldb, ldc, M, N, K, mode, head, hof;
    float scale;
};
struct TCParams { TCDesc d[24]; };

constexpr int ST_EL = 10240;
constexpr int ST_BY = 20480;
constexpr int MM_SMEM = 2 * ST_BY;

__global__ __launch_bounds__(256) void mma_gemm(TCParams p) {
    TCDesc d = p.d[blockIdx.z];
    const int m0 = blockIdx.y * 64, n0 = blockIdx.x * 64;
    if (m0 >= d.M || n0 >= d.N) return;

    extern __shared__ __align__(16) bf16 sm[];
    const int t = threadIdx.x, lane = t & 31, w = t >> 5;
    const int mrow = (w & 1) * 32, ncol = (w >> 1) * 16;

    const int ar = t >> 2, acl = (t & 3) * 8;
    const bf16* pAh = d.Ah + d.hof + (size_t)(m0 + ar) * d.lda + acl;
    const bf16* pAl = d.Al + d.hof + (size_t)(m0 + ar) * d.lda + acl;
    const bf16* pBh = d.Bh + d.hof + (size_t)(n0 + ar) * d.ldb + acl;
    const bf16* pBl = d.Bl + d.hof + (size_t)(n0 + ar) * d.ldb + acl;

    const uint32_t ub = smem_u32(sm);
    const int aR = mrow + (lane & 15), aC = (lane >> 4) * 8;
    const int bR = ncol + (lane & 7) + ((lane & 16) >> 1), bC = lane & 8;
    uint32_t adAh[2], adAl[2];
#pragma unroll
    for (int mt = 0; mt < 2; mt++) {
        adAh[mt] = ub + ((aR + mt*16)*40 + aC)*2;
        adAl[mt] = ub + 5120 + ((aR + mt*16)*40 + aC)*2;
    }
    const uint32_t adBh = ub + 10240 + (bR*40 + bC)*2;
    const uint32_t adBl = ub + 15360 + (bR*40 + bC)*2;
    const int stA = ar*40 + acl;

    float acc[2][2][4];
#pragma unroll
    for (int mt = 0; mt < 2; mt++)
#pragma unroll
        for (int nt = 0; nt < 2; nt++)
#pragma unroll
            for (int i = 0; i < 4; i++) acc[mt][nt][i] = 0.f;

    uint4 vh0, vl0, wh, wl;
    vh0 = *(const uint4*)(pAh);
    vl0 = *(const uint4*)(pAl);
    wh  = *(const uint4*)(pBh);
    wl  = *(const uint4*)(pBl);
    *(uint4*)&sm[stA]        = vh0;
    *(uint4*)&sm[2560 + stA] = vl0;
    *(uint4*)&sm[5120 + stA] = wh;
    *(uint4*)&sm[7680 + stA] = wl;
    __syncthreads();

    const int nkt = d.K >> 5;
    for (int kt = 0; kt < nkt; kt++) {
        const bool more = (kt + 1) < nkt;
        if (more) {
            const int k0 = (kt + 1) * 32;
            vh0 = *(const uint4*)(pAh + k0);
            vl0 = *(const uint4*)(pAl + k0);
            wh  = *(const uint4*)(pBh + k0);
            wl  = *(const uint4*)(pBl + k0);
        }
        const uint32_t so = (uint32_t)(kt & 1) * ST_BY;
#pragma unroll
        for (int ks = 0; ks < 2; ks++) {
            uint32_t fAh[2][4], fAl[2][4], fBh[2][2], fBl[2][2];
#pragma unroll
            for (int mt = 0; mt < 2; mt++) {
                ldm4(fAh[mt], adAh[mt] + so + ks*32);
                ldm4(fAl[mt], adAl[mt] + so + ks*32);
            }
            {
                uint32_t tb[4];
                ldm4(tb, adBh + so + ks*32);
                fBh[0][0] = tb[0]; fBh[0][1] = tb[1];
                fBh[1][0] = tb[2]; fBh[1][1] = tb[3];
                ldm4(tb, adBl + so + ks*32);
                fBl[0][0] = tb[0]; fBl[0][1] = tb[1];
                fBl[1][0] = tb[2]; fBl[1][1] = tb[3];
            }
#pragma unroll
            for (int term = 0; term < 3; term++)
#pragma unroll
                for (int mt = 0; mt < 2; mt++)
#pragma unroll
                    for (int nt = 0; nt < 2; nt++)
                        mma16816(acc[mt][nt],
                                 (term == 2) ? fAl[mt] : fAh[mt],
                                 (term == 1) ? fBl[nt] : fBh[nt]);
        }
        if (more) {
            const int eo = ((kt + 1) & 1) * ST_EL;
            *(uint4*)&sm[eo + stA]        = vh0;
            *(uint4*)&sm[eo + 2560 + stA] = vl0;
            *(uint4*)&sm[eo + 5120 + stA] = wh;
            *(uint4*)&sm[eo + 7680 + stA] = wl;
            __syncthreads();
        }
    }

#pragma unroll
    for (int mt = 0; mt < 2; mt++)
#pragma unroll
        for (int nt = 0; nt < 2; nt++) {
            int r = m0 + mrow + mt*16 + (lane >> 2);
            int c = n0 + ncol + nt*8 + (lane & 3)*2;
            float* a4 = acc[mt][nt];
            if (d.mode == 1) {
                d.C[((size_t)r*NM + c)*8 + d.head]       = 1.f/(1.f+expf(-a4[0]));
                d.C[((size_t)r*NM + c+1)*8 + d.head]     = 1.f/(1.f+expf(-a4[1]));
                d.C[((size_t)(r+8)*NM + c)*8 + d.head]   = 1.f/(1.f+expf(-a4[2]));
                d.C[((size_t)(r+8)*NM + c+1)*8 + d.head] = 1.f/(1.f+expf(-a4[3]));
            } else {
                float b0v = d.bias ? d.bias[c] : 0.f;
                float b1v = d.bias ? d.bias[c+1] : 0.f;
                float vv[4] = {d.scale*(a4[0]+b0v), d.scale*(a4[1]+b1v),
                               d.scale*(a4[2]+b0v), d.scale*(a4[3]+b1v)};
                size_t ix[4] = {(size_t)r*d.ldc + c, (size_t)r*d.ldc + c+1,
                                (size_t)(r+8)*d.ldc + c, (size_t)(r+8)*d.ldc + c+1};
                if (d.mode == 0) {
#pragma unroll
                    for (int u = 0; u < 4; u++) d.C[ix[u]] = vv[u];
                } else {
#pragma unroll
                    for (int u = 0; u < 4; u++) {
                        bf16 hh = __float2bfloat16(vv[u]);
                        d.Chi[ix[u]] = hh;
                        d.Clo[ix[u]] = __float2bfloat16(vv[u] - __bfloat162float(hh));
                    }
                }
            }
        }
}

// ---------------- conversion work helpers -----------------------------------
struct RMDesc { const float* a; const float* a2; bf16* hi; bf16* lo; int n4; };
__device__ __forceinline__ void rm_work(const RMDesc& d, int i) {
    if (i >= d.n4) return;
    float4 x = ((const float4*)d.a)[i];
    if (d.a2) {
        float4 y = ((const float4*)d.a2)[i];
        x.x -= y.x; x.y -= y.y; x.z -= y.z; x.w -= y.w;
    }
    float v[4] = {x.x, x.y, x.z, x.w};
    __nv_bfloat162 H[2], L[2];
#pragma unroll
    for (int k = 0; k < 2; k++) {
        bf16 h0 = __float2bfloat16(v[2*k]), h1 = __float2bfloat16(v[2*k+1]);
        H[k] = __halves2bfloat162(h0, h1);
        L[k] = __halves2bfloat162(__float2bfloat16(v[2*k]   - __bfloat162float(h0)),
                                  __float2bfloat16(v[2*k+1] - __bfloat162float(h1)));
    }
    ((__nv_bfloat162*)d.hi)[i*2] = H[0]; ((__nv_bfloat162*)d.hi)[i*2+1] = H[1];
    ((__nv_bfloat162*)d.lo)[i*2] = L[0]; ((__nv_bfloat162*)d.lo)[i*2+1] = L[1];
}

struct TRDesc { const float* src; bf16* hi; bf16* lo; int K, N; };
__device__ __forceinline__ void tr_work(const TRDesc& d, int bx, int by, int t) {
    int n0 = bx * 32, k0 = by * 32;
    if (n0 >= d.N || k0 >= d.K) return;
    __shared__ float tl[32][33];
    int tx = t & 31, ty = t >> 5;
#pragma unroll
    for (int r = 0; r < 4; r++)
        tl[ty + r*8][tx] = d.src[(size_t)(k0 + ty + r*8) * d.N + n0 + tx];
    __syncthreads();
#pragma unroll
    for (int r = 0; r < 4; r++) {
        int n = n0 + ty + r*8, k = k0 + tx;
        float x = tl[tx][ty + r*8];
        bf16 h = __float2bfloat16(x);
        d.hi[(size_t)n * d.K + k] = h;
        d.lo[(size_t)n * d.K + k] = __float2bfloat16(x - __bfloat162float(h));
    }
}

// ---------------- conv1: all input splits + weight transposes (1 launch) ----
struct C1Params { RMDesc rm[4]; TRDesc tr[8]; };
__global__ __launch_bounds__(256) void conv1(C1Params p) {
    const int z = blockIdx.z, t = threadIdx.x;
    if (z < 4) {
        rm_work(p.rm[z], (blockIdx.y * 24 + blockIdx.x) * 256 + t);
    } else {
        tr_work(p.tr[z - 4], blockIdx.x, blockIdx.y, t);
    }
}

// ---------------- conv2: rm2 diff/tp splits + W01^T + b01 partials ----------
__global__ __launch_bounds__(256) void conv2(
    const float* __restrict__ ip, const float* __restrict__ tp,
    bf16* __restrict__ dh, bf16* __restrict__ dl,
    bf16* __restrict__ tph, bf16* __restrict__ tpl,
    const float* __restrict__ W01, bf16* __restrict__ w01h, bf16* __restrict__ w01l,
    const float* __restrict__ bo, const float* __restrict__ W1,
    const float* __restrict__ biv, float* __restrict__ part) {
    const int z = blockIdx.z, t = threadIdx.x;
    const int idx = blockIdx.y * 24 + blockIdx.x;
    if (z == 0) {
        RMDesc d = {ip, tp, dh, dl, 512*768/4};
        rm_work(d, idx * 256 + t);
    } else if (z == 1) {
        RMDesc d = {tp, 0, tph, tpl, 512*768/4};
        rm_work(d, idx * 256 + t);
    } else {
        if (idx < 192) {
            TRDesc d = {W01, w01h, w01l, 768, 256};
            tr_work(d, idx & 7, idx >> 3, t);
        } else if (idx < 240) {
            int b = idx - 192;
            int kc = (b % 24) * 32;
            const float* vec = (b < 24) ? bo : biv;
            const float* Wm  = (b < 24) ? W1 : W01;
            float s = 0.f;
#pragma unroll
            for (int k = 0; k < 32; k++)
                s = fmaf(vec[kc + k], Wm[(size_t)(kc + k)*256 + t], s);
            part[b*256 + t] = s;
        }
    }
}

// ---------------- fused tail v3, term-outer mma -----------------------------
constexpr int FUSE_SMEM = 102400 + 9744;

__global__ __launch_bounds__(256) void fuse2(
    const float* __restrict__ Ah_g, const float* __restrict__ At_g,
    const float* __restrict__ part, const float* __restrict__ b1,
    const float* __restrict__ wbuf, const bf16* __restrict__ W2Th,
    const bf16* __restrict__ W2Tl, const float* __restrict__ b2,
    const float* __restrict__ W3, const float* __restrict__ b3,
    float* __restrict__ out) {

    extern __shared__ __align__(16) char fsm[];
    bf16* sWh = (bf16*)fsm;
    bf16* sWl = sWh + 20480;
    bf16* sHh = sWl + 20480;
    bf16* sHl = sHh + 5120;
    float* sAf = (float*)(sHl + 5120);
    float* sBm = sAf + 2048;
    float* sb2 = sBm + 256;
    float* sW3 = sb2 + 64;
    float* sb3 = sW3 + 64;

    const int m = blockIdx.x, t = threadIdx.x, lane = t & 31, w = t >> 5;
    const int rn = t & 127, jh = t >> 7;
    const int wn = t >> 2, wseg = t & 3;

#pragma unroll
    for (int jc = 0; jc < 8; jc++) {
        *(uint4*)&sWh[jc*2560 + wn*40 + wseg*8] = *(const uint4*)&W2Th[wn*256 + jc*32 + wseg*8];
        *(uint4*)&sWl[jc*2560 + wn*40 + wseg*8] = *(const uint4*)&W2Tl[wn*256 + jc*32 + wseg*8];
    }
    {
        const float4* Ag = (const float4*)(Ah_g + (size_t)m*2048);
        ((float4*)sAf)[t]       = Ag[t];
        ((float4*)sAf)[t + 256] = Ag[t + 256];
    }
    {
        float s = b1[t];
#pragma unroll
        for (int i = 0; i < 48; i++) s += part[i*256 + t];
#pragma unroll
        for (int h8 = 0; h8 < 8; h8++) s += At_g[(size_t)m*2048 + h8*256 + t];
        sBm[t] = s;
    }
    if (t < 64) { sb2[t] = b2[t]; sW3[t] = W3[t]; }
    if (t == 0) sb3[0] = b3[0];
    __syncthreads();

    const uint32_t uHh = smem_u32(sHh), uHl = smem_u32(sHl);
    const uint32_t uWh = smem_u32(sWh), uWl = smem_u32(sWl);
    const uint32_t adAh = uHh + ((w*16 + (lane & 15))*40 + (lane >> 4)*8)*2;
    const uint32_t adAl = uHl + ((w*16 + (lane & 15))*40 + (lane >> 4)*8)*2;
    const int bR = (lane & 7) + ((lane & 16) >> 1), bC = lane & 8;

    for (int half = 0; half < 2; half++) {
        const int n = half*128 + rn;
        const float4* wp = (const float4*)(wbuf + ((size_t)n*NM + m)*8);
        float4 wA = wp[0], wB = wp[1];
        ull wd[8];
        DUP2(wd[0], wA.x); DUP2(wd[1], wA.y); DUP2(wd[2], wA.z); DUP2(wd[3], wA.w);
        DUP2(wd[4], wB.x); DUP2(wd[5], wB.y); DUP2(wd[6], wB.z); DUP2(wd[7], wB.w);

        float acc[8][4];
#pragma unroll
        for (int nt = 0; nt < 8; nt++)
#pragma unroll
            for (int i = 0; i < 4; i++) acc[nt][i] = 0.f;

        for (int jc = 0; jc < 8; jc++) {
            const int j0 = jc * 32;
            ull hacc[8];
#pragma unroll
            for (int i = 0; i < 8; i++) hacc[i] = *(const ull*)&sBm[j0 + jh*16 + 2*i];
#pragma unroll
            for (int h8 = 0; h8 < 8; h8++)
#pragma unroll
                for (int i = 0; i < 8; i++)
                    FMA2(hacc[i], wd[h8], *(const ull*)&sAf[h8*256 + j0 + jh*16 + 2*i]);
            uint32_t hp[8], lp[8];
#pragma unroll
            for (int i = 0; i < 8; i++) {
                float f0, f1;
                UNPK2(f0, f1, hacc[i]);
                f0 = fmaxf(f0, 0.f); f1 = fmaxf(f1, 0.f);
                bf16 h0 = __float2bfloat16(f0), h1 = __float2bfloat16(f1);
                bf16 l0 = __float2bfloat16(f0 - __bfloat162float(h0));
                bf16 l1 = __float2bfloat16(f1 - __bfloat162float(h1));
                __nv_bfloat162 hx = __halves2bfloat162(h0, h1);
                __nv_bfloat162 lx = __halves2bfloat162(l0, l1);
                hp[i] = *(uint32_t*)&hx;
                lp[i] = *(uint32_t*)&lx;
            }
            __syncthreads();
            {
                bf16* dsth = &sHh[rn*40 + jh*16];
                bf16* dstl = &sHl[rn*40 + jh*16];
                *(uint4*)dsth       = make_uint4(hp[0], hp[1], hp[2], hp[3]);
                *(uint4*)(dsth + 8) = make_uint4(hp[4], hp[5], hp[6], hp[7]);
                *(uint4*)dstl       = make_uint4(lp[0], lp[1], lp[2], lp[3]);
                *(uint4*)(dstl + 8) = make_uint4(lp[4], lp[5], lp[6], lp[7]);
            }
            __syncthreads();

            const uint32_t wjc = (uint32_t)jc * 5120;
#pragma unroll
            for (int ks = 0; ks < 2; ks++) {
                uint32_t fAh[4], fAl[4], fBh[8][2], fBl[8][2];
                ldm4(fAh, adAh + ks*32);
                ldm4(fAl, adAl + ks*32);
#pragma unroll
                for (int pr = 0; pr < 4; pr++) {
                    uint32_t tb[4];
                    ldm4(tb, uWh + wjc + ((pr*16 + bR)*40 + bC)*2 + ks*32);
                    fBh[2*pr][0] = tb[0]; fBh[2*pr][1]   = tb[1];
                    fBh[2*pr+1][0] = tb[2]; fBh[2*pr+1][1] = tb[3];
                    ldm4(tb, uWl + wjc + ((pr*16 + bR)*40 + bC)*2 + ks*32);
                    fBl[2*pr][0] = tb[0]; fBl[2*pr][1]   = tb[1];
                    fBl[2*pr+1][0] = tb[2]; fBl[2*pr+1][1] = tb[3];
                }
#pragma unroll
                for (int term = 0; term < 3; term++)
#pragma unroll
                    for (int nt = 0; nt < 8; nt++)
                        mma16816(acc[nt],
                                 (term == 2) ? fAl : fAh,
                                 (term == 1) ? fBl[nt] : fBh[nt]);
            }
        }

        float s0 = 0.f, s1 = 0.f;
#pragma unroll
        for (int nt = 0; nt < 8; nt++) {
            int c0 = nt*8 + 2*(lane & 3);
            float w30 = sW3[c0], w31 = sW3[c0+1];
            float bb0 = sb2[c0], bb1 = sb2[c0+1];
            s0 = fmaf(fmaxf(acc[nt][0] + bb0, 0.f), w30, s0);
            s0 = fmaf(fmaxf(acc[nt][1] + bb1, 0.f), w31, s0);
            s1 = fmaf(fmaxf(acc[nt][2] + bb0, 0.f), w30, s1);
            s1 = fmaf(fmaxf(acc[nt][3] + bb1, 0.f), w31, s1);
        }
        s0 += __shfl_xor_sync(0xFFFFFFFF, s0, 1);
        s0 += __shfl_xor_sync(0xFFFFFFFF, s0, 2);
        s1 += __shfl_xor_sync(0xFFFFFFFF, s1, 1);
        s1 += __shfl_xor_sync(0xFFFFFFFF, s1, 2);
        if ((lane & 3) == 0) {
            int r0 = half*128 + w*16 + (lane >> 2);
            out[(size_t)r0*NM + m]     = 0.5f * tanhf(s0 + sb3[0]);
            out[(size_t)(r0+8)*NM + m] = 0.5f * tanhf(s1 + sb3[0]);
        }
    }
}

// ---------------- launch ----------------------------------------------------
extern "C" void kernel_launch(void* const* d_in, const int* in_sizes, int n_in,
                              void* d_out, int out_size) {
    const float* Q   = (const float*)d_in[0];
    const float* IMG = (const float*)d_in[1];
    const float* TGT = (const float*)d_in[2];
    const float* Wq  = (const float*)d_in[3];
    const float* bq  = (const float*)d_in[4];
    const float* Wi  = (const float*)d_in[5];
    const float* bi  = (const float*)d_in[6];
    const float* Wt  = (const float*)d_in[7];
    const float* bt  = (const float*)d_in[8];
    const float* Wiq = (const float*)d_in[9];
    const float* biq = (const float*)d_in[10];
    const float* Wik = (const float*)d_in[11];
    const float* Wiv = (const float*)d_in[13];
    const float* biv = (const float*)d_in[14];
    const float* Wo  = (const float*)d_in[15];
    const float* bo  = (const float*)d_in[16];
    const float* W1  = (const float*)d_in[17];
    const float* b1  = (const float*)d_in[18];
    const float* W2  = (const float*)d_in[19];
    const float* b2  = (const float*)d_in[20];
    const float* W3  = (const float*)d_in[21];
    const float* b3  = (const float*)d_in[22];
    float* out = (float*)d_out;

    float* F; bf16* B;
    cudaGetSymbolAddress((void**)&F, g_f);
    cudaGetSymbolAddress((void**)&B, g_b);
    float *ip = F+F_ip, *tp = F+F_tp;
    float *W01 = F+F_W01, *part = F+F_part;
    float *Ah = F+F_Ah, *At = F+F_At, *wb = F+F_w;

    cudaFuncSetAttribute(mma_gemm, cudaFuncAttributeMaxDynamicSharedMemorySize, MM_SMEM);
    cudaFuncSetAttribute(fuse2, cudaFuncAttributeMaxDynamicSharedMemorySize, FUSE_SMEM);

#define HI(off) (B + (off))
#define LO(off, sz) (B + (off) + (sz))
    const float scale = 1.0f / sqrtf(96.0f);

    // 1: conv1 = all row-major splits + all weight transposes (one launch)
    C1Params c1 = {};
    c1.rm[0] = {Q,   0, HI(B_Qs),   LO(B_Qs,   256*768), 256*768/4};
    c1.rm[1] = {IMG, 0, HI(B_IMGs), LO(B_IMGs, 512*768), 512*768/4};
    c1.rm[2] = {TGT, 0, HI(B_TGTs), LO(B_TGTs, 512*768), 512*768/4};
    c1.rm[3] = {Wo,  0, HI(B_Wos),  LO(B_Wos,  768*768), 768*768/4};
    c1.tr[0] = {Wq,  HI(B_WqT),  LO(B_WqT,  768*768), 768, 768};
    c1.tr[1] = {Wi,  HI(B_WiT),  LO(B_WiT,  768*768), 768, 768};
    c1.tr[2] = {Wt,  HI(B_WtT),  LO(B_WtT,  768*768), 768, 768};
    c1.tr[3] = {Wiq, HI(B_WiqT), LO(B_WiqT, 768*768), 768, 768};
    c1.tr[4] = {Wik, HI(B_WikT), LO(B_WikT, 768*768), 768, 768};
    c1.tr[5] = {Wiv, HI(B_WivT), LO(B_WivT, 768*768), 768, 768};
    c1.tr[6] = {W1,  HI(B_W1T),  LO(B_W1T,  256*768), 768, 256};
    c1.tr[7] = {W2,  HI(B_W2T),  LO(B_W2T,  64*256),  256, 64};
    conv1<<<dim3(24, 24, 12), 256>>>(c1);

    // 2: L1 projections (q split-direct) + W01 = Wo@W1
    TCParams p1 = {};
    p1.d[0] = {HI(B_Qs),   LO(B_Qs,  256*768), HI(B_WqT), LO(B_WqT, 768*768), bq, 0,
               HI(B_qs), LO(B_qs, 256*768), 768, 768, 768, 256, 768, 768, 2, 0, 0, 1.f};
    p1.d[1] = {HI(B_IMGs), LO(B_IMGs,512*768), HI(B_WiT), LO(B_WiT, 768*768), bi, ip,
               0, 0, 768, 768, 768, 512, 768, 768, 0, 0, 0, 1.f};
    p1.d[2] = {HI(B_TGTs), LO(B_TGTs,512*768), HI(B_WtT), LO(B_WtT, 768*768), bt, tp,
               0, 0, 768, 768, 768, 512, 768, 768, 0, 0, 0, 1.f};
    p1.d[3] = {HI(B_Wos),  LO(B_Wos, 768*768), HI(B_W1T), LO(B_W1T, 256*768), 0, W01,
               0, 0, 768, 768, 256, 768, 256, 768, 0, 0, 0, 1.f};
    mma_gemm<<<dim3(12, 12, 4), 256, MM_SMEM>>>(p1);

    // 3: conv2 = diff/tp splits + W01^T split + b01 partials
    conv2<<<dim3(24, 16, 3), 256>>>(ip, tp, HI(B_dps), LO(B_dps, 512*768),
                                    HI(B_tps), LO(B_tps, 512*768),
                                    W01, HI(B_W01T), LO(B_W01T, 256*768),
                                    bo, W1, biv, part);

    // 4: L2: qh, kd, vd, vt — bf16 split outputs
    TCParams p2 = {};
    p2.d[0] = {HI(B_qs),  LO(B_qs, 256*768), HI(B_WiqT), LO(B_WiqT, 768*768), biq, 0,
               HI(B_qhs), LO(B_qhs, 256*768), 768, 768, 768, 256, 768, 768, 2, 0, 0, scale};
    p2.d[1] = {HI(B_dps), LO(B_dps,512*768), HI(B_WikT), LO(B_WikT, 768*768), 0, 0,
               HI(B_kds), LO(B_kds, 512*768), 768, 768, 768, 512, 768, 768, 2, 0, 0, 1.f};
    p2.d[2] = {HI(B_dps), LO(B_dps,512*768), HI(B_WivT), LO(B_WivT, 768*768), 0, 0,
               HI(B_vds), LO(B_vds, 512*768), 768, 768, 768, 512, 768, 768, 2, 0, 0, 1.f};
    p2.d[3] = {HI(B_tps), LO(B_tps,512*768), HI(B_WivT), LO(B_WivT, 768*768), 0, 0,
               HI(B_vts), LO(B_vts, 512*768), 768, 768, 768, 512, 768, 768, 2, 0, 0, 1.f};
    mma_gemm<<<dim3(12, 8, 4), 256, MM_SMEM>>>(p2);

    // 5: L34 = logits (8 heads, sigmoid scatter) + 16 per-head A GEMMs
    TCParams p34 = {};
    for (int h = 0; h < 8; h++) {
        p34.d[h] = {HI(B_qhs), LO(B_qhs, 256*768), HI(B_kds), LO(B_kds, 512*768), 0, wb,
                    0, 0, 768, 768, 0, 256, 512, 96, 1, h, h*96, 1.f};
        p34.d[8+h]  = {HI(B_vds) + h*96, LO(B_vds, 512*768) + h*96,
                       HI(B_W01T) + h*96, LO(B_W01T, 256*768) + h*96, 0,
                       Ah + h*256, 0, 0, 768, 768, 2048, 512, 256, 96, 0, 0, 0, 1.f};
        p34.d[16+h] = {HI(B_vts) + h*96, LO(B_vts, 512*768) + h*96,
                       HI(B_W01T) + h*96, LO(B_W01T, 256*768) + h*96, 0,
                       At + h*256, 0, 0, 768, 768, 2048, 512, 256, 96, 0, 0, 0, 1.f};
    }
    mma_gemm<<<dim3(8, 8, 24), 256, MM_SMEM>>>(p34);

    // 6: fused tail (inline Bm = b1 + sum part + sum_h At)
    fuse2<<<NM, 256, FUSE_SMEM>>>(Ah, At, part, b1, wb,
                                  HI(B_W2T), LO(B_W2T, 64*256),
                                  b2, W3, b3, out);
}

// round 16
// speedup vs baseline: 1.2426x; 1.2426x over previous
#include <cuda_runtime.h>
#include <cuda_fp16.h>
#include <cstdint>
#include <cmath>

typedef unsigned long long ull;
typedef __half h16;
#define DM 768
#define NQ 256
#define NM 512

#define FMA2(acc, a, b) asm("fma.rn.f32x2 %0, %1, %2, %0;" : "+l"(acc) : "l"(a), "l"(b))
#define DUP2(d, s)      asm("mov.b64 %0, {%1, %1};" : "=l"(d) : "f"(s))
#define UNPK2(lo, hi, s) asm("mov.b64 {%0, %1}, %2;" : "=f"(lo), "=f"(hi) : "l"(s))

__device__ __forceinline__ uint32_t smem_u32(const void* p) {
    uint32_t a;
    asm("{ .reg .u64 t; cvta.to.shared.u64 t, %1; cvt.u32.u64 %0, t; }" : "=r"(a) : "l"(p));
    return a;
}
__device__ __forceinline__ void ldm4(uint32_t* r, uint32_t addr) {
    asm volatile("ldmatrix.sync.aligned.m8n8.x4.shared.b16 {%0,%1,%2,%3}, [%4];"
        : "=r"(r[0]), "=r"(r[1]), "=r"(r[2]), "=r"(r[3]) : "r"(addr));
}
__device__ __forceinline__ void mma16816(float* c, const uint32_t* a, const uint32_t* b) {
    asm volatile("mma.sync.aligned.m16n8k16.row.col.f32.f16.f16.f32 "
        "{%0,%1,%2,%3}, {%4,%5,%6,%7}, {%8,%9}, {%0,%1,%2,%3};"
        : "+f"(c[0]), "+f"(c[1]), "+f"(c[2]), "+f"(c[3])
        : "r"(a[0]), "r"(a[1]), "r"(a[2]), "r"(a[3]), "r"(b[0]), "r"(b[1]));
}

// ---------------- scratch ---------------------------------------------------
constexpr size_t F_ip   = 0;
constexpr size_t F_tp   = F_ip   + 512*768;
constexpr size_t F_W01  = F_tp   + 512*768;
constexpr size_t F_part = F_W01  + 768*256;
constexpr size_t F_Ah   = F_part + 48*256;
constexpr size_t F_At   = F_Ah   + 512*2048;
constexpr size_t F_w    = F_At   + 512*2048;
constexpr size_t F_END  = F_w    + 256*512*8;
__device__ __align__(16) float g_f[F_END];

constexpr size_t B_Qs   = 0;
constexpr size_t B_IMGs = B_Qs   + 2*256*768;
constexpr size_t B_TGTs = B_IMGs + 2*512*768;
constexpr size_t B_Wos  = B_TGTs + 2*512*768;
constexpr size_t B_WqT  = B_Wos  + 2*768*768;
constexpr size_t B_WiT  = B_WqT  + 2*768*768;
constexpr size_t B_WtT  = B_WiT  + 2*768*768;
constexpr size_t B_WiqT = B_WtT  + 2*768*768;
constexpr size_t B_WikT = B_WiqT + 2*768*768;
constexpr size_t B_WivT = B_WikT + 2*768*768;
constexpr size_t B_W1T  = B_WivT + 2*768*768;
constexpr size_t B_W2T  = B_W1T  + 2*256*768;
constexpr size_t B_qs   = B_W2T  + 2*64*256;
constexpr size_t B_dps  = B_qs   + 2*256*768;
constexpr size_t B_tps  = B_dps  + 2*512*768;
constexpr size_t B_qhs  = B_tps  + 2*512*768;
constexpr size_t B_kds  = B_qhs  + 2*256*768;
constexpr size_t B_vds  = B_kds  + 2*512*768;
constexpr size_t B_vts  = B_vds  + 2*512*768;
constexpr size_t B_W01T = B_vts  + 2*512*768;
constexpr size_t B_END  = B_W01T + 2*256*768;
__device__ __align__(16) h16 g_b[B_END];

// ---------------- fp16 2-term MMA GEMM: 128x64, 2-stage pipelined -----------
// C = scale*( Ahi@Bhi^T + Alo@Bhi^T + bias ).  B-lo is never loaded.
// Stage (h16 elems): Ah@0 [128][40], Al@5120, Bh@10240 [64][40].
// ldmatrix byte offsets: Al 10240B, Bh 20480B.
struct TCDesc {
    const h16 *Ah, *Al, *Bh, *Bl;
    const float* bias;
    float* C;
    h16 *Chi, *Clo;
    int lda, ldb, ldc, M, N, K, mode, head, hof;
    float scale;
};
struct TCParams { TCDesc d[24]; };

constexpr int ST_EL = 12800;
constexpr int ST_BY = 25600;
constexpr int MM_SMEM = 2 * ST_BY;

__global__ __launch_bounds__(256) void mma_gemm(TCParams p) {
    TCDesc d = p.d[blockIdx.z];
    const int m0 = blockIdx.y * 128, n0 = blockIdx.x * 64;
    if (m0 >= d.M || n0 >= d.N) return;

    extern __shared__ __align__(16) h16 sm[];
    const int t = threadIdx.x, lane = t & 31, w = t >> 5;
    const int mrow = (w & 3) * 32, ncol = (w >> 2) * 32;

    const int ar = t >> 2, acl = (t & 3) * 8;
    const h16* pAh = d.Ah + d.hof + (size_t)(m0 + ar) * d.lda + acl;
    const h16* pAl = d.Al + d.hof + (size_t)(m0 + ar) * d.lda + acl;
    const h16* pBh = d.Bh + d.hof + (size_t)(n0 + ar) * d.ldb + acl;
    const size_t a64 = (size_t)64 * d.lda;

    const uint32_t ub = smem_u32(sm);
    const int aR = mrow + (lane & 15), aC = (lane >> 4) * 8;
    const int bR = ncol + (lane & 7) + ((lane & 16) >> 1), bC = lane & 8;
    uint32_t adAh[2], adAl[2], adBh[2];
#pragma unroll
    for (int mt = 0; mt < 2; mt++) {
        adAh[mt] = ub + ((aR + mt*16)*40 + aC)*2;
        adAl[mt] = ub + 10240 + ((aR + mt*16)*40 + aC)*2;
    }
#pragma unroll
    for (int pr = 0; pr < 2; pr++)
        adBh[pr] = ub + 20480 + ((bR + pr*16)*40 + bC)*2;
    const int stA = ar*40 + acl;

    float acc[2][4][4];
#pragma unroll
    for (int mt = 0; mt < 2; mt++)
#pragma unroll
        for (int nt = 0; nt < 4; nt++)
#pragma unroll
            for (int i = 0; i < 4; i++) acc[mt][nt][i] = 0.f;

    uint4 vh0, vh1, vl0, vl1, wh;
    vh0 = *(const uint4*)(pAh);
    vh1 = *(const uint4*)(pAh + a64);
    vl0 = *(const uint4*)(pAl);
    vl1 = *(const uint4*)(pAl + a64);
    wh  = *(const uint4*)(pBh);
    *(uint4*)&sm[stA]               = vh0;
    *(uint4*)&sm[2560 + stA]        = vh1;
    *(uint4*)&sm[5120 + stA]        = vl0;
    *(uint4*)&sm[5120 + 2560 + stA] = vl1;
    *(uint4*)&sm[10240 + stA]       = wh;
    __syncthreads();

    const int nkt = d.K >> 5;
    for (int kt = 0; kt < nkt; kt++) {
        const bool more = (kt + 1) < nkt;
        if (more) {
            const int k0 = (kt + 1) * 32;
            vh0 = *(const uint4*)(pAh + k0);
            vh1 = *(const uint4*)(pAh + a64 + k0);
            vl0 = *(const uint4*)(pAl + k0);
            vl1 = *(const uint4*)(pAl + a64 + k0);
            wh  = *(const uint4*)(pBh + k0);
        }
        const uint32_t so = (uint32_t)(kt & 1) * ST_BY;
#pragma unroll
        for (int ks = 0; ks < 2; ks++) {
            uint32_t fAh[2][4], fAl[2][4], fBh[4][2];
#pragma unroll
            for (int mt = 0; mt < 2; mt++) {
                ldm4(fAh[mt], adAh[mt] + so + ks*32);
                ldm4(fAl[mt], adAl[mt] + so + ks*32);
            }
#pragma unroll
            for (int pr = 0; pr < 2; pr++) {
                uint32_t tb[4];
                ldm4(tb, adBh[pr] + so + ks*32);
                fBh[2*pr][0] = tb[0]; fBh[2*pr][1]   = tb[1];
                fBh[2*pr+1][0] = tb[2]; fBh[2*pr+1][1] = tb[3];
            }
#pragma unroll
            for (int term = 0; term < 2; term++)
#pragma unroll
                for (int mt = 0; mt < 2; mt++)
#pragma unroll
                    for (int nt = 0; nt < 4; nt++)
                        mma16816(acc[mt][nt],
                                 term ? fAl[mt] : fAh[mt], fBh[nt]);
        }
        if (more) {
            const int eo = ((kt + 1) & 1) * ST_EL;
            *(uint4*)&sm[eo + stA]               = vh0;
            *(uint4*)&sm[eo + 2560 + stA]        = vh1;
            *(uint4*)&sm[eo + 5120 + stA]        = vl0;
            *(uint4*)&sm[eo + 5120 + 2560 + stA] = vl1;
            *(uint4*)&sm[eo + 10240 + stA]       = wh;
            __syncthreads();
        }
    }

#pragma unroll
    for (int mt = 0; mt < 2; mt++)
#pragma unroll
        for (int nt = 0; nt < 4; nt++) {
            int r = m0 + mrow + mt*16 + (lane >> 2);
            int c = n0 + ncol + nt*8 + (lane & 3)*2;
            float* a4 = acc[mt][nt];
            if (d.mode == 1) {
                d.C[((size_t)r*NM + c)*8 + d.head]       = 1.f/(1.f+expf(-a4[0]));
                d.C[((size_t)r*NM + c+1)*8 + d.head]     = 1.f/(1.f+expf(-a4[1]));
                d.C[((size_t)(r+8)*NM + c)*8 + d.head]   = 1.f/(1.f+expf(-a4[2]));
                d.C[((size_t)(r+8)*NM + c+1)*8 + d.head] = 1.f/(1.f+expf(-a4[3]));
            } else {
                float b0v = d.bias ? d.bias[c] : 0.f;
                float b1v = d.bias ? d.bias[c+1] : 0.f;
                float vv[4] = {d.scale*(a4[0]+b0v), d.scale*(a4[1]+b1v),
                               d.scale*(a4[2]+b0v), d.scale*(a4[3]+b1v)};
                size_t ix[4] = {(size_t)r*d.ldc + c, (size_t)r*d.ldc + c+1,
                                (size_t)(r+8)*d.ldc + c, (size_t)(r+8)*d.ldc + c+1};
                if (d.mode == 0) {
#pragma unroll
                    for (int u = 0; u < 4; u++) d.C[ix[u]] = vv[u];
                } else {
#pragma unroll
                    for (int u = 0; u < 4; u++) {
                        h16 hh = __float2half_rn(vv[u]);
                        d.Chi[ix[u]] = hh;
                        d.Clo[ix[u]] = __float2half_rn(vv[u] - __half2float(hh));
                    }
                }
            }
        }
}

// ---------------- conversion work helpers -----------------------------------
struct RMDesc { const float* a; const float* a2; h16* hi; h16* lo; int n4; };
__device__ __forceinline__ void rm_work(const RMDesc& d, int i) {
    if (i >= d.n4) return;
    float4 x = ((const float4*)d.a)[i];
    if (d.a2) {
        float4 y = ((const float4*)d.a2)[i];
        x.x -= y.x; x.y -= y.y; x.z -= y.z; x.w -= y.w;
    }
    float v[4] = {x.x, x.y, x.z, x.w};
    __half2 H[2], L[2];
#pragma unroll
    for (int k = 0; k < 2; k++) {
        h16 h0 = __float2half_rn(v[2*k]), h1 = __float2half_rn(v[2*k+1]);
        H[k] = __halves2half2(h0, h1);
        L[k] = __halves2half2(__float2half_rn(v[2*k]   - __half2float(h0)),
                              __float2half_rn(v[2*k+1] - __half2float(h1)));
    }
    ((__half2*)d.hi)[i*2] = H[0]; ((__half2*)d.hi)[i*2+1] = H[1];
    ((__half2*)d.lo)[i*2] = L[0]; ((__half2*)d.lo)[i*2+1] = L[1];
}

struct TRDesc { const float* src; h16* hi; h16* lo; int K, N; };
__device__ __forceinline__ void tr_work(const TRDesc& d, int bx, int by, int t) {
    int n0 = bx * 32, k0 = by * 32;
    if (n0 >= d.N || k0 >= d.K) return;
    __shared__ float tl[32][33];
    int tx = t & 31, ty = t >> 5;
#pragma unroll
    for (int r = 0; r < 4; r++)
        tl[ty + r*8][tx] = d.src[(size_t)(k0 + ty + r*8) * d.N + n0 + tx];
    __syncthreads();
#pragma unroll
    for (int r = 0; r < 4; r++) {
        int n = n0 + ty + r*8, k = k0 + tx;
        float x = tl[tx][ty + r*8];
        h16 h = __float2half_rn(x);
        d.hi[(size_t)n * d.K + k] = h;
        d.lo[(size_t)n * d.K + k] = __float2half_rn(x - __half2float(h));
    }
}

// ---------------- conv1: all input splits + weight transposes (1 launch) ----
struct C1Params { RMDesc rm[4]; TRDesc tr[8]; };
__global__ __launch_bounds__(256) void conv1(C1Params p) {
    const int z = blockIdx.z, t = threadIdx.x;
    if (z < 4) {
        rm_work(p.rm[z], (blockIdx.y * 24 + blockIdx.x) * 256 + t);
    } else {
        tr_work(p.tr[z - 4], blockIdx.x, blockIdx.y, t);
    }
}

// ---------------- conv2: rm2 diff/tp splits + W01^T + b01 partials ----------
__global__ __launch_bounds__(256) void conv2(
    const float* __restrict__ ip, const float* __restrict__ tp,
    h16* __restrict__ dh, h16* __restrict__ dl,
    h16* __restrict__ tph, h16* __restrict__ tpl,
    const float* __restrict__ W01, h16* __restrict__ w01h, h16* __restrict__ w01l,
    const float* __restrict__ bo, const float* __restrict__ W1,
    const float* __restrict__ biv, float* __restrict__ part) {
    const int z = blockIdx.z, t = threadIdx.x;
    const int idx = blockIdx.y * 24 + blockIdx.x;
    if (z == 0) {
        RMDesc d = {ip, tp, dh, dl, 512*768/4};
        rm_work(d, idx * 256 + t);
    } else if (z == 1) {
        RMDesc d = {tp, 0, tph, tpl, 512*768/4};
        rm_work(d, idx * 256 + t);
    } else {
        if (idx < 192) {
            TRDesc d = {W01, w01h, w01l, 768, 256};
            tr_work(d, idx & 7, idx >> 3, t);
        } else if (idx < 240) {
            int b = idx - 192;
            int kc = (b % 24) * 32;
            const float* vec = (b < 24) ? bo : biv;
            const float* Wm  = (b < 24) ? W1 : W01;
            float s = 0.f;
#pragma unroll
            for (int k = 0; k < 32; k++)
                s = fmaf(vec[kc + k], Wm[(size_t)(kc + k)*256 + t], s);
            part[b*256 + t] = s;
        }
    }
}

// ---------------- fused tail: fp16 2-term -----------------------------------
// smem: sWh [8][64][40]=20480 h16, sHh 5120, sHl 5120, then floats.
constexpr int FUSE_SMEM = (20480 + 5120 + 5120) * 2 + 9744;

__global__ __launch_bounds__(256) void fuse2(
    const float* __restrict__ Ah_g, const float* __restrict__ At_g,
    const float* __restrict__ part, const float* __restrict__ b1,
    const float* __restrict__ wbuf, const h16* __restrict__ W2Th,
    const float* __restrict__ b2, const float* __restrict__ W3,
    const float* __restrict__ b3, float* __restrict__ out) {

    extern __shared__ __align__(16) char fsm[];
    h16* sWh = (h16*)fsm;
    h16* sHh = sWh + 20480;
    h16* sHl = sHh + 5120;
    float* sAf = (float*)(sHl + 5120);
    float* sBm = sAf + 2048;
    float* sb2 = sBm + 256;
    float* sW3 = sb2 + 64;
    float* sb3 = sW3 + 64;

    const int m = blockIdx.x, t = threadIdx.x, lane = t & 31, w = t >> 5;
    const int rn = t & 127, jh = t >> 7;
    const int wn = t >> 2, wseg = t & 3;

#pragma unroll
    for (int jc = 0; jc < 8; jc++)
        *(uint4*)&sWh[jc*2560 + wn*40 + wseg*8] = *(const uint4*)&W2Th[wn*256 + jc*32 + wseg*8];
    {
        const float4* Ag = (const float4*)(Ah_g + (size_t)m*2048);
        ((float4*)sAf)[t]       = Ag[t];
        ((float4*)sAf)[t + 256] = Ag[t + 256];
    }
    {
        float s = b1[t];
#pragma unroll
        for (int i = 0; i < 48; i++) s += part[i*256 + t];
#pragma unroll
        for (int h8 = 0; h8 < 8; h8++) s += At_g[(size_t)m*2048 + h8*256 + t];
        sBm[t] = s;
    }
    if (t < 64) { sb2[t] = b2[t]; sW3[t] = W3[t]; }
    if (t == 0) sb3[0] = b3[0];
    __syncthreads();

    const uint32_t uHh = smem_u32(sHh), uHl = smem_u32(sHl);
    const uint32_t uWh = smem_u32(sWh);
    const uint32_t adAh = uHh + ((w*16 + (lane & 15))*40 + (lane >> 4)*8)*2;
    const uint32_t adAl = uHl + ((w*16 + (lane & 15))*40 + (lane >> 4)*8)*2;
    const int bR = (lane & 7) + ((lane & 16) >> 1), bC = lane & 8;

    for (int half = 0; half < 2; half++) {
        const int n = half*128 + rn;
        const float4* wp = (const float4*)(wbuf + ((size_t)n*NM + m)*8);
        float4 wA = wp[0], wB = wp[1];
        ull wd[8];
        DUP2(wd[0], wA.x); DUP2(wd[1], wA.y); DUP2(wd[2], wA.z); DUP2(wd[3], wA.w);
        DUP2(wd[4], wB.x); DUP2(wd[5], wB.y); DUP2(wd[6], wB.z); DUP2(wd[7], wB.w);

        float acc[8][4];
#pragma unroll
        for (int nt = 0; nt < 8; nt++)
#pragma unroll
            for (int i = 0; i < 4; i++) acc[nt][i] = 0.f;

        for (int jc = 0; jc < 8; jc++) {
            const int j0 = jc * 32;
            ull hacc[8];
#pragma unroll
            for (int i = 0; i < 8; i++) hacc[i] = *(const ull*)&sBm[j0 + jh*16 + 2*i];
#pragma unroll
            for (int h8 = 0; h8 < 8; h8++)
#pragma unroll
                for (int i = 0; i < 8; i++)
                    FMA2(hacc[i], wd[h8], *(const ull*)&sAf[h8*256 + j0 + jh*16 + 2*i]);
            uint32_t hp[8], lp[8];
#pragma unroll
            for (int i = 0; i < 8; i++) {
                float f0, f1;
                UNPK2(f0, f1, hacc[i]);
                f0 = fmaxf(f0, 0.f); f1 = fmaxf(f1, 0.f);
                h16 h0 = __float2half_rn(f0), h1 = __float2half_rn(f1);
                h16 l0 = __float2half_rn(f0 - __half2float(h0));
                h16 l1 = __float2half_rn(f1 - __half2float(h1));
                __half2 hx = __halves2half2(h0, h1);
                __half2 lx = __halves2half2(l0, l1);
                hp[i] = *(uint32_t*)&hx;
                lp[i] = *(uint32_t*)&lx;
            }
            __syncthreads();
            {
                h16* dsth = &sHh[rn*40 + jh*16];
                h16* dstl = &sHl[rn*40 + jh*16];
                *(uint4*)dsth       = make_uint4(hp[0], hp[1], hp[2], hp[3]);
                *(uint4*)(dsth + 8) = make_uint4(hp[4], hp[5], hp[6], hp[7]);
                *(uint4*)dstl       = make_uint4(lp[0], lp[1], lp[2], lp[3]);
                *(uint4*)(dstl + 8) = make_uint4(lp[4], lp[5], lp[6], lp[7]);
            }
            __syncthreads();

            const uint32_t wjc = (uint32_t)jc * 5120;
#pragma unroll
            for (int ks = 0; ks < 2; ks++) {
                uint32_t fAh[4], fAl[4], fBh[8][2];
                ldm4(fAh, adAh + ks*32);
                ldm4(fAl, adAl + ks*32);
#pragma unroll
                for (int pr = 0; pr < 4; pr++) {
                    uint32_t tb[4];
                    ldm4(tb, uWh + wjc + ((pr*16 + bR)*40 + bC)*2 + ks*32);
                    fBh[2*pr][0] = tb[0]; fBh[2*pr][1]   = tb[1];
                    fBh[2*pr+1][0] = tb[2]; fBh[2*pr+1][1] = tb[3];
                }
#pragma unroll
                for (int term = 0; term < 2; term++)
#pragma unroll
                    for (int nt = 0; nt < 8; nt++)
                        mma16816(acc[nt], term ? fAl : fAh, fBh[nt]);
            }
        }

        float s0 = 0.f, s1 = 0.f;
#pragma unroll
        for (int nt = 0; nt < 8; nt++) {
            int c0 = nt*8 + 2*(lane & 3);
            float w30 = sW3[c0], w31 = sW3[c0+1];
            float bb0 = sb2[c0], bb1 = sb2[c0+1];
            s0 = fmaf(fmaxf(acc[nt][0] + bb0, 0.f), w30, s0);
            s0 = fmaf(fmaxf(acc[nt][1] + bb1, 0.f), w31, s0);
            s1 = fmaf(fmaxf(acc[nt][2] + bb0, 0.f), w30, s1);
            s1 = fmaf(fmaxf(acc[nt][3] + bb1, 0.f), w31, s1);
        }
        s0 += __shfl_xor_sync(0xFFFFFFFF, s0, 1);
        s0 += __shfl_xor_sync(0xFFFFFFFF, s0, 2);
        s1 += __shfl_xor_sync(0xFFFFFFFF, s1, 1);
        s1 += __shfl_xor_sync(0xFFFFFFFF, s1, 2);
        if ((lane & 3) == 0) {
            int r0 = half*128 + w*16 + (lane >> 2);
            out[(size_t)r0*NM + m]     = 0.5f * tanhf(s0 + sb3[0]);
            out[(size_t)(r0+8)*NM + m] = 0.5f * tanhf(s1 + sb3[0]);
        }
    }
}

// ---------------- launch ----------------------------------------------------
extern "C" void kernel_launch(void* const* d_in, const int* in_sizes, int n_in,
                              void* d_out, int out_size) {
    const float* Q   = (const float*)d_in[0];
    const float* IMG = (const float*)d_in[1];
    const float* TGT = (const float*)d_in[2];
    const float* Wq  = (const float*)d_in[3];
    const float* bq  = (const float*)d_in[4];
    const float* Wi  = (const float*)d_in[5];
    const float* bi  = (const float*)d_in[6];
    const float* Wt  = (const float*)d_in[7];
    const float* bt  = (const float*)d_in[8];
    const float* Wiq = (const float*)d_in[9];
    const float* biq = (const float*)d_in[10];
    const float* Wik = (const float*)d_in[11];
    const float* Wiv = (const float*)d_in[13];
    const float* biv = (const float*)d_in[14];
    const float* Wo  = (const float*)d_in[15];
    const float* bo  = (const float*)d_in[16];
    const float* W1  = (const float*)d_in[17];
    const float* b1  = (const float*)d_in[18];
    const float* W2  = (const float*)d_in[19];
    const float* b2  = (const float*)d_in[20];
    const float* W3  = (const float*)d_in[21];
    const float* b3  = (const float*)d_in[22];
    float* out = (float*)d_out;

    float* F; h16* B;
    cudaGetSymbolAddress((void**)&F, g_f);
    cudaGetSymbolAddress((void**)&B, g_b);
    float *ip = F+F_ip, *tp = F+F_tp;
    float *W01 = F+F_W01, *part = F+F_part;
    float *Ah = F+F_Ah, *At = F+F_At, *wb = F+F_w;

    cudaFuncSetAttribute(mma_gemm, cudaFuncAttributeMaxDynamicSharedMemorySize, MM_SMEM);
    cudaFuncSetAttribute(fuse2, cudaFuncAttributeMaxDynamicSharedMemorySize, FUSE_SMEM);

#define HI(off) (B + (off))
#define LO(off, sz) (B + (off) + (sz))
    const float scale = 1.0f / sqrtf(96.0f);

    // 1: conv1 = all row-major splits + all weight transposes (one launch)
    C1Params c1 = {};
    c1.rm[0] = {Q,   0, HI(B_Qs),   LO(B_Qs,   256*768), 256*768/4};
    c1.rm[1] = {IMG, 0, HI(B_IMGs), LO(B_IMGs, 512*768), 512*768/4};
    c1.rm[2] = {TGT, 0, HI(B_TGTs), LO(B_TGTs, 512*768), 512*768/4};
    c1.rm[3] = {Wo,  0, HI(B_Wos),  LO(B_Wos,  768*768), 768*768/4};
    c1.tr[0] = {Wq,  HI(B_WqT),  LO(B_WqT,  768*768), 768, 768};
    c1.tr[1] = {Wi,  HI(B_WiT),  LO(B_WiT,  768*768), 768, 768};
    c1.tr[2] = {Wt,  HI(B_WtT),  LO(B_WtT,  768*768), 768, 768};
    c1.tr[3] = {Wiq, HI(B_WiqT), LO(B_WiqT, 768*768), 768, 768};
    c1.tr[4] = {Wik, HI(B_WikT), LO(B_WikT, 768*768), 768, 768};
    c1.tr[5] = {Wiv, HI(B_WivT), LO(B_WivT, 768*768), 768, 768};
    c1.tr[6] = {W1,  HI(B_W1T),  LO(B_W1T,  256*768), 768, 256};
    c1.tr[7] = {W2,  HI(B_W2T),  LO(B_W2T,  64*256),  256, 64};
    conv1<<<dim3(24, 24, 12), 256>>>(c1);

    // 2: L1 projections (q split-direct) + W01 = Wo@W1
    TCParams p1 = {};
    p1.d[0] = {HI(B_Qs),   LO(B_Qs,  256*768), HI(B_WqT), 0, bq, 0,
               HI(B_qs), LO(B_qs, 256*768), 768, 768, 768, 256, 768, 768, 2, 0, 0, 1.f};
    p1.d[1] = {HI(B_IMGs), LO(B_IMGs,512*768), HI(B_WiT), 0, bi, ip,
               0, 0, 768, 768, 768, 512, 768, 768, 0, 0, 0, 1.f};
    p1.d[2] = {HI(B_TGTs), LO(B_TGTs,512*768), HI(B_WtT), 0, bt, tp,
               0, 0, 768, 768, 768, 512, 768, 768, 0, 0, 0, 1.f};
    p1.d[3] = {HI(B_Wos),  LO(B_Wos, 768*768), HI(B_W1T), 0, 0, W01,
               0, 0, 768, 768, 256, 768, 256, 768, 0, 0, 0, 1.f};
    mma_gemm<<<dim3(12, 6, 4), 256, MM_SMEM>>>(p1);

    // 3: conv2 = diff/tp splits + W01^T split + b01 partials
    conv2<<<dim3(24, 16, 3), 256>>>(ip, tp, HI(B_dps), LO(B_dps, 512*768),
                                    HI(B_tps), LO(B_tps, 512*768),
                                    W01, HI(B_W01T), LO(B_W01T, 256*768),
                                    bo, W1, biv, part);

    // 4: L2: qh, kd, vd, vt — fp16 split outputs
    TCParams p2 = {};
    p2.d[0] = {HI(B_qs),  LO(B_qs, 256*768), HI(B_WiqT), 0, biq, 0,
               HI(B_qhs), LO(B_qhs, 256*768), 768, 768, 768, 256, 768, 768, 2, 0, 0, scale};
    p2.d[1] = {HI(B_dps), LO(B_dps,512*768), HI(B_WikT), 0, 0, 0,
               HI(B_kds), LO(B_kds, 512*768), 768, 768, 768, 512, 768, 768, 2, 0, 0, 1.f};
    p2.d[2] = {HI(B_dps), LO(B_dps,512*768), HI(B_WivT), 0, 0, 0,
               HI(B_vds), LO(B_vds, 512*768), 768, 768, 768, 512, 768, 768, 2, 0, 0, 1.f};
    p2.d[3] = {HI(B_tps), LO(B_tps,512*768), HI(B_WivT), 0, 0, 0,
               HI(B_vts), LO(B_vts, 512*768), 768, 768, 768, 512, 768, 768, 2, 0, 0, 1.f};
    mma_gemm<<<dim3(12, 4, 4), 256, MM_SMEM>>>(p2);

    // 5: L34 = logits (8 heads, sigmoid scatter) + 16 per-head A GEMMs
    TCParams p34 = {};
    for (int h = 0; h < 8; h++) {
        p34.d[h] = {HI(B_qhs), LO(B_qhs, 256*768), HI(B_kds), 0, 0, wb,
                    0, 0, 768, 768, 0, 256, 512, 96, 1, h, h*96, 1.f};
        p34.d[8+h]  = {HI(B_vds) + h*96, LO(B_vds, 512*768) + h*96,
                       HI(B_W01T) + h*96, 0, 0,
                       Ah + h*256, 0, 0, 768, 768, 2048, 512, 256, 96, 0, 0, 0, 1.f};
        p34.d[16+h] = {HI(B_vts) + h*96, LO(B_vts, 512*768) + h*96,
                       HI(B_W01T) + h*96, 0, 0,
                       At + h*256, 0, 0, 768, 768, 2048, 512, 256, 96, 0, 0, 0, 1.f};
    }
    mma_gemm<<<dim3(8, 4, 24), 256, MM_SMEM>>>(p34);

    // 6: fused tail (inline Bm = b1 + sum part + sum_h At)
    fuse2<<<NM, 256, FUSE_SMEM>>>(Ah, At, part, b1, wb,
                                  HI(B_W2T), b2, W3, b3, out);
}